// round 5
// baseline (speedup 1.0000x reference)
#include <cuda_runtime.h>
#include <math.h>
#include <math_constants.h>

#define N_NODES 30000
#define N_EDGES 480000
#define E_TOT   (N_EDGES + N_NODES)

// ---------------- scratch -----------------------------------------------------
__device__ float g_xl1[N_NODES * 128];
__device__ float g_xr1[N_NODES * 128];
__device__ float g_h1 [N_NODES * 128];
__device__ float g_xl2[N_NODES * 256];
__device__ float g_xr2[N_NODES * 256];

__device__ int g_deg     [N_NODES];      // statically zero; scan re-zeroes each call
__device__ int g_rowstart[N_NODES + 1];
__device__ int g_cursor  [N_NODES];
__device__ int g_csr_src [E_TOT];

__device__ __forceinline__ float lrelu(float v) { return v > 0.0f ? v : 0.2f * v; }

// ---------------- f32x2 packed helpers ----------------------------------------
__device__ __forceinline__ unsigned long long pk2(float x, float y) {
    unsigned long long r;
    asm("mov.b64 %0, {%1, %2};" : "=l"(r) : "f"(x), "f"(y));
    return r;
}
__device__ __forceinline__ void fma2(unsigned long long& d,
                                     unsigned long long a, unsigned long long b) {
    asm("fma.rn.f32x2 %0, %1, %2, %0;" : "+l"(d) : "l"(a), "l"(b));
}
__device__ __forceinline__ float2 unpk(unsigned long long v) {
    float2 f;
    asm("mov.b64 {%0, %1}, %2;" : "=f"(f.x), "=f"(f.y) : "l"(v));
    return f;
}
__device__ __forceinline__ void lds2(unsigned long long& a0, unsigned long long& a1,
                                     unsigned sa) {
    asm("ld.shared.v2.b64 {%0, %1}, [%2];" : "=l"(a0), "=l"(a1) : "r"(sa));
}

// ---------------- kernel 0: gemm1_dual (+norm) FUSED with dst histogram --------
// blocks [0, gblocks): layer-1 dual GEMM with inline min-max normalization
// blocks [gblocks, gblocks+hblocks): histogram of dst (+self loops) into g_deg
__global__ __launch_bounds__(256) void gemm1_hist(
        const float* __restrict__ x, const float* __restrict__ lb,
        const float* __restrict__ ub,
        const float* __restrict__ Wl, const float* __restrict__ bl,
        const float* __restrict__ Wr, const float* __restrict__ br,
        const int* __restrict__ dst, int E, int n, int gblocks) {
    int tid = threadIdx.x;
    if ((int)blockIdx.x >= gblocks) {
        int e = ((int)blockIdx.x - gblocks) * 256 + tid;
        if (e < E + n) {
            int d = (e < E) ? __ldg(dst + e) : e - E;
            atomicAdd(&g_deg[d], 1);
        }
        return;
    }
    __shared__ float4 sA[32][4];
    int row0 = blockIdx.x * 32;
    for (int i = tid; i < 32 * 4; i += 256) {
        int r = i >> 2, kk = i & 3;
        int row = row0 + r;
        float4 v = (row < n) ? ((const float4*)x)[row * 4 + kk]
                             : make_float4(0.f, 0.f, 0.f, 0.f);
        float4 l4 = ((const float4*)lb)[kk];
        float4 u4 = ((const float4*)ub)[kk];
        v.x = (v.x - l4.x) / (u4.x - l4.x);
        v.y = (v.y - l4.y) / (u4.y - l4.y);
        v.z = (v.z - l4.z) / (u4.z - l4.z);
        v.w = (v.w - l4.w) / (u4.w - l4.w);
        sA[r][kk] = v;
    }
    __syncthreads();
    int mat = tid >> 7, col = tid & 127;
    const float* W = mat ? Wr : Wl;
    float bb = (mat ? br : bl)[col];
    float* outp = mat ? g_xr1 : g_xl1;
    float acc[32];
#pragma unroll
    for (int r = 0; r < 32; r++) acc[r] = bb;
#pragma unroll
    for (int k4 = 0; k4 < 4; k4++) {
        float w0 = W[(size_t)(k4 * 4 + 0) * 128 + col];
        float w1 = W[(size_t)(k4 * 4 + 1) * 128 + col];
        float w2 = W[(size_t)(k4 * 4 + 2) * 128 + col];
        float w3 = W[(size_t)(k4 * 4 + 3) * 128 + col];
#pragma unroll
        for (int r = 0; r < 32; r++) {
            float4 a = sA[r][k4];
            acc[r] += a.x * w0 + a.y * w1 + a.z * w2 + a.w * w3;
        }
    }
#pragma unroll
    for (int r = 0; r < 32; r++) {
        int row = row0 + r;
        if (row < n) outp[(size_t)row * 128 + col] = acc[r];
    }
}

// ---------------- scan (single block); also re-zeroes g_deg for next replay ----
__global__ void scan_kernel(int n) {
    __shared__ int warp_sums[32];
    __shared__ int s_carry;
    if (threadIdx.x == 0) s_carry = 0;
    __syncthreads();
    int lane = threadIdx.x & 31, wid = threadIdx.x >> 5;
    for (int base = 0; base < n; base += 1024) {
        int i = base + (int)threadIdx.x;
        int v = (i < n) ? g_deg[i] : 0;
        if (i < n) g_deg[i] = 0;           // reset for the next graph replay
        int x = v;
#pragma unroll
        for (int o = 1; o < 32; o <<= 1) {
            int t = __shfl_up_sync(0xFFFFFFFFu, x, o);
            if (lane >= o) x += t;
        }
        if (lane == 31) warp_sums[wid] = x;
        __syncthreads();
        if (wid == 0) {
            int s = warp_sums[lane];
#pragma unroll
            for (int o = 1; o < 32; o <<= 1) {
                int t = __shfl_up_sync(0xFFFFFFFFu, s, o);
                if (lane >= o) s += t;
            }
            warp_sums[lane] = s;
        }
        __syncthreads();
        int excl = x - v + (wid > 0 ? warp_sums[wid - 1] : 0) + s_carry;
        if (i < n) { g_rowstart[i] = excl; g_cursor[i] = excl; }
        __syncthreads();
        if (threadIdx.x == 0) s_carry += warp_sums[31];
        __syncthreads();
    }
    if (threadIdx.x == 0) g_rowstart[n] = s_carry;
}

__global__ void scatter_kernel(const int* __restrict__ src, const int* __restrict__ dst,
                               int E, int n) {
    int e = blockIdx.x * blockDim.x + threadIdx.x;
    if (e >= E + n) return;
    int s, d;
    if (e < E) { s = __ldg(src + e); d = __ldg(dst + e); }
    else       { s = d = e - E; }
    int pos = atomicAdd(&g_cursor[d], 1);
    g_csr_src[pos] = s;
}

// ---------------- fused GAT layer 1: 2 warps per node, no-max softmax ----------
// 64 threads per node; warp `half` handles a contiguous half of the edge range.
// Partials (den, acc) are additive (no running max) -> single smem merge.
__global__ __launch_bounds__(256) void gat_layer1(const float* __restrict__ att,
                                                  const float* __restrict__ bias, int n) {
    __shared__ float4 s_acc[4][32];
    __shared__ float  s_den[4][32];
    int local = threadIdx.x >> 6;
    int node  = blockIdx.x * 4 + local;
    int half  = (threadIdx.x >> 5) & 1;
    int lane  = threadIdx.x & 31;
    bool valid = node < n;

    float4 t4 = ((const float4*)att)[lane];
    float4 x4 = make_float4(0.f, 0.f, 0.f, 0.f);
    int beg = 0, end = 0;
    if (valid) {
        beg = g_rowstart[node];
        end = g_rowstart[node + 1];
        x4 = ((const float4*)g_xr1)[(size_t)node * 32 + lane];
    }
    int mid = beg + ((end - beg + 1) >> 1);
    int lo = half ? mid : beg;
    int hi = half ? end : mid;

    float den = 0.0f;
    float4 acc = make_float4(0.f, 0.f, 0.f, 0.f);

    int i = lo;
    for (; i + 2 <= hi; i += 2) {
        int s0 = __ldg(g_csr_src + i), s1 = __ldg(g_csr_src + i + 1);
        float4 a0 = ((const float4*)g_xl1)[(size_t)s0 * 32 + lane];
        float4 a1 = ((const float4*)g_xl1)[(size_t)s1 * 32 + lane];
        float p0 = lrelu(a0.x + x4.x) * t4.x + lrelu(a0.y + x4.y) * t4.y
                 + lrelu(a0.z + x4.z) * t4.z + lrelu(a0.w + x4.w) * t4.w;
        float p1 = lrelu(a1.x + x4.x) * t4.x + lrelu(a1.y + x4.y) * t4.y
                 + lrelu(a1.z + x4.z) * t4.z + lrelu(a1.w + x4.w) * t4.w;
        p0 += __shfl_xor_sync(0xFFFFFFFFu, p0, 1);
        p1 += __shfl_xor_sync(0xFFFFFFFFu, p1, 1);
        p0 += __shfl_xor_sync(0xFFFFFFFFu, p0, 2);
        p1 += __shfl_xor_sync(0xFFFFFFFFu, p1, 2);
        p0 += __shfl_xor_sync(0xFFFFFFFFu, p0, 4);
        p1 += __shfl_xor_sync(0xFFFFFFFFu, p1, 4);
        float e0 = __expf(p0), e1 = __expf(p1);
        den += e0 + e1;
        acc.x += e0 * a0.x + e1 * a1.x;
        acc.y += e0 * a0.y + e1 * a1.y;
        acc.z += e0 * a0.z + e1 * a1.z;
        acc.w += e0 * a0.w + e1 * a1.w;
    }
    if (i < hi) {
        int s0 = __ldg(g_csr_src + i);
        float4 a0 = ((const float4*)g_xl1)[(size_t)s0 * 32 + lane];
        float p0 = lrelu(a0.x + x4.x) * t4.x + lrelu(a0.y + x4.y) * t4.y
                 + lrelu(a0.z + x4.z) * t4.z + lrelu(a0.w + x4.w) * t4.w;
        p0 += __shfl_xor_sync(0xFFFFFFFFu, p0, 1);
        p0 += __shfl_xor_sync(0xFFFFFFFFu, p0, 2);
        p0 += __shfl_xor_sync(0xFFFFFFFFu, p0, 4);
        float e0 = __expf(p0);
        den += e0;
        acc.x += e0 * a0.x; acc.y += e0 * a0.y;
        acc.z += e0 * a0.z; acc.w += e0 * a0.w;
    }

    if (half == 1) { s_acc[local][lane] = acc; s_den[local][lane] = den; }
    __syncthreads();
    if (half == 0 && valid) {
        float4 o2 = s_acc[local][lane];
        acc.x += o2.x; acc.y += o2.y; acc.z += o2.z; acc.w += o2.w;
        den += s_den[local][lane];
        float inv = 1.0f / den;
        float4 b4 = ((const float4*)bias)[lane];
        float4 o;
        o.x = fmaxf(acc.x * inv + b4.x, 0.f);
        o.y = fmaxf(acc.y * inv + b4.y, 0.f);
        o.z = fmaxf(acc.z * inv + b4.z, 0.f);
        o.w = fmaxf(acc.w * inv + b4.w, 0.f);
        ((float4*)g_h1)[(size_t)node * 32 + lane] = o;
    }
}

// ---------------- layer-2 dual GEMM, f32x2-packed (K=128, NC=256 each) ---------
__global__ __launch_bounds__(512) void gemm2_dual(
        const float* __restrict__ Wl, const float* __restrict__ bl,
        const float* __restrict__ Wr, const float* __restrict__ br, int n) {
    __shared__ __align__(16) float2 sAP[32][128];   // [row-pair][k]
    int row0 = blockIdx.x * 64;
    int tid = threadIdx.x;
    for (int i = tid; i < 64 * 32; i += 512) {
        int r = i >> 5, k4 = i & 31;
        int row = row0 + r;
        float4 v = (row < n) ? ((const float4*)g_h1)[(size_t)row * 32 + k4]
                             : make_float4(0.f, 0.f, 0.f, 0.f);
        int r2 = r >> 1, h = r & 1;
        ((float*)&sAP[r2][4 * k4 + 0])[h] = v.x;
        ((float*)&sAP[r2][4 * k4 + 1])[h] = v.y;
        ((float*)&sAP[r2][4 * k4 + 2])[h] = v.z;
        ((float*)&sAP[r2][4 * k4 + 3])[h] = v.w;
    }
    __syncthreads();

    int mat = tid >> 8, c = tid & 255;
    const float* W = mat ? Wr : Wl;
    float bb = (mat ? br : bl)[c];
    float* outp = mat ? g_xr2 : g_xl2;

    unsigned long long acc[32];
    unsigned long long bp = pk2(bb, bb);
#pragma unroll
    for (int r2 = 0; r2 < 32; r2++) acc[r2] = bp;

    unsigned sbase;
    { void* p = &sAP[0][0]; sbase = (unsigned)__cvta_generic_to_shared(p); }

#pragma unroll 2
    for (int k2 = 0; k2 < 64; k2++) {
        int k = 2 * k2;
        float w0 = W[(size_t)k * 256 + c];
        float w1 = W[(size_t)(k + 1) * 256 + c];
        unsigned long long wp0 = pk2(w0, w0);
        unsigned long long wp1 = pk2(w1, w1);
#pragma unroll
        for (int r2 = 0; r2 < 32; r2++) {
            unsigned long long a0, a1;
            lds2(a0, a1, sbase + (unsigned)((r2 * 128 + k) << 3));
            fma2(acc[r2], a0, wp0);
            fma2(acc[r2], a1, wp1);
        }
    }

#pragma unroll
    for (int r2 = 0; r2 < 32; r2++) {
        float2 f = unpk(acc[r2]);
        int ra = row0 + 2 * r2, rb = ra + 1;
        if (ra < n) outp[(size_t)ra * 256 + c] = f.x;
        if (rb < n) outp[(size_t)rb * 256 + c] = f.y;
    }
}

// ---------------- fused GAT layer 2 + head-mean + 64->5 head + sigmoid ---------
// 2 warps per node, additive partial merge through smem.
__global__ __launch_bounds__(256) void gat_layer2(const float* __restrict__ att,
                                                  const float* __restrict__ bias2,
                                                  const float* __restrict__ W3,
                                                  const float* __restrict__ b3,
                                                  float* __restrict__ out, int n) {
    __shared__ float4 s_acc[4][64];
    __shared__ float  s_den[4][32];
    int local = threadIdx.x >> 6;
    int node  = blockIdx.x * 4 + local;
    int half  = (threadIdx.x >> 5) & 1;
    int lane  = threadIdx.x & 31;
    bool valid = node < n;

    float4 tA = ((const float4*)att)[lane * 2], tB = ((const float4*)att)[lane * 2 + 1];
    float4 xA = make_float4(0.f, 0.f, 0.f, 0.f), xB = xA;
    int beg = 0, end = 0;
    if (valid) {
        beg = g_rowstart[node];
        end = g_rowstart[node + 1];
        const float4* xr4 = (const float4*)g_xr2 + (size_t)node * 64;
        xA = xr4[lane * 2]; xB = xr4[lane * 2 + 1];
    }
    int mid = beg + ((end - beg + 1) >> 1);
    int lo = half ? mid : beg;
    int hi = half ? end : mid;

    float den = 0.0f;
    float4 accA = make_float4(0.f, 0.f, 0.f, 0.f);
    float4 accB = make_float4(0.f, 0.f, 0.f, 0.f);

    int i = lo;
    for (; i + 2 <= hi; i += 2) {
        int s0 = __ldg(g_csr_src + i), s1 = __ldg(g_csr_src + i + 1);
        const float4* p0l = (const float4*)g_xl2 + (size_t)s0 * 64;
        const float4* p1l = (const float4*)g_xl2 + (size_t)s1 * 64;
        float4 aA0 = p0l[lane * 2], aB0 = p0l[lane * 2 + 1];
        float4 aA1 = p1l[lane * 2], aB1 = p1l[lane * 2 + 1];
        float p0 = lrelu(aA0.x + xA.x) * tA.x + lrelu(aA0.y + xA.y) * tA.y
                 + lrelu(aA0.z + xA.z) * tA.z + lrelu(aA0.w + xA.w) * tA.w
                 + lrelu(aB0.x + xB.x) * tB.x + lrelu(aB0.y + xB.y) * tB.y
                 + lrelu(aB0.z + xB.z) * tB.z + lrelu(aB0.w + xB.w) * tB.w;
        float p1 = lrelu(aA1.x + xA.x) * tA.x + lrelu(aA1.y + xA.y) * tA.y
                 + lrelu(aA1.z + xA.z) * tA.z + lrelu(aA1.w + xA.w) * tA.w
                 + lrelu(aB1.x + xB.x) * tB.x + lrelu(aB1.y + xB.y) * tB.y
                 + lrelu(aB1.z + xB.z) * tB.z + lrelu(aB1.w + xB.w) * tB.w;
        p0 += __shfl_xor_sync(0xFFFFFFFFu, p0, 1);
        p1 += __shfl_xor_sync(0xFFFFFFFFu, p1, 1);
        p0 += __shfl_xor_sync(0xFFFFFFFFu, p0, 2);
        p1 += __shfl_xor_sync(0xFFFFFFFFu, p1, 2);
        p0 += __shfl_xor_sync(0xFFFFFFFFu, p0, 4);
        p1 += __shfl_xor_sync(0xFFFFFFFFu, p1, 4);
        float e0 = __expf(p0), e1 = __expf(p1);
        den += e0 + e1;
        accA.x += e0 * aA0.x + e1 * aA1.x; accA.y += e0 * aA0.y + e1 * aA1.y;
        accA.z += e0 * aA0.z + e1 * aA1.z; accA.w += e0 * aA0.w + e1 * aA1.w;
        accB.x += e0 * aB0.x + e1 * aB1.x; accB.y += e0 * aB0.y + e1 * aB1.y;
        accB.z += e0 * aB0.z + e1 * aB1.z; accB.w += e0 * aB0.w + e1 * aB1.w;
    }
    if (i < hi) {
        int s0 = __ldg(g_csr_src + i);
        const float4* p0l = (const float4*)g_xl2 + (size_t)s0 * 64;
        float4 aA0 = p0l[lane * 2], aB0 = p0l[lane * 2 + 1];
        float p0 = lrelu(aA0.x + xA.x) * tA.x + lrelu(aA0.y + xA.y) * tA.y
                 + lrelu(aA0.z + xA.z) * tA.z + lrelu(aA0.w + xA.w) * tA.w
                 + lrelu(aB0.x + xB.x) * tB.x + lrelu(aB0.y + xB.y) * tB.y
                 + lrelu(aB0.z + xB.z) * tB.z + lrelu(aB0.w + xB.w) * tB.w;
        p0 += __shfl_xor_sync(0xFFFFFFFFu, p0, 1);
        p0 += __shfl_xor_sync(0xFFFFFFFFu, p0, 2);
        p0 += __shfl_xor_sync(0xFFFFFFFFu, p0, 4);
        float e0 = __expf(p0);
        den += e0;
        accA.x += e0 * aA0.x; accA.y += e0 * aA0.y;
        accA.z += e0 * aA0.z; accA.w += e0 * aA0.w;
        accB.x += e0 * aB0.x; accB.y += e0 * aB0.y;
        accB.z += e0 * aB0.z; accB.w += e0 * aB0.w;
    }

    if (half == 1) {
        s_acc[local][lane * 2] = accA;
        s_acc[local][lane * 2 + 1] = accB;
        s_den[local][lane] = den;
    }
    __syncthreads();
    if (half == 0 && valid) {
        float4 oA = s_acc[local][lane * 2], oB = s_acc[local][lane * 2 + 1];
        accA.x += oA.x; accA.y += oA.y; accA.z += oA.z; accA.w += oA.w;
        accB.x += oB.x; accB.y += oB.y; accB.z += oB.z; accB.w += oB.w;
        den += s_den[local][lane];
        float inv = 1.0f / den;
        float v[8] = { accA.x * inv, accA.y * inv, accA.z * inv, accA.w * inv,
                       accB.x * inv, accB.y * inv, accB.z * inv, accB.w * inv };
#pragma unroll
        for (int j = 0; j < 8; j++) {
            v[j] += __shfl_xor_sync(0xFFFFFFFFu, v[j], 8);
            v[j] += __shfl_xor_sync(0xFFFFFFFFu, v[j], 16);
        }
        int g = lane & 7;
        float part[5] = {0.f, 0.f, 0.f, 0.f, 0.f};
#pragma unroll
        for (int j = 0; j < 8; j++) {
            int feat = g * 8 + j;
            float hv = fmaxf(0.25f * v[j] + __ldg(bias2 + feat), 0.f);
#pragma unroll
            for (int o = 0; o < 5; o++)
                part[o] += hv * __ldg(W3 + feat * 5 + o);
        }
#pragma unroll
        for (int o = 0; o < 5; o++) {
            part[o] += __shfl_xor_sync(0xFFFFFFFFu, part[o], 1);
            part[o] += __shfl_xor_sync(0xFFFFFFFFu, part[o], 2);
            part[o] += __shfl_xor_sync(0xFFFFFFFFu, part[o], 4);
        }
        if (lane == 0) {
#pragma unroll
            for (int o = 0; o < 5; o++) {
                float z = part[o] + __ldg(b3 + o);
                out[(size_t)node * 5 + o] = 1.0f / (1.0f + __expf(-z));
            }
        }
    }
}

// ---------------- launch --------------------------------------------------------
extern "C" void kernel_launch(void* const* d_in, const int* in_sizes, int n_in,
                              void* d_out, int out_size) {
    const float* x     = (const float*)d_in[0];
    const int*   ei    = (const int*)  d_in[1];
    const float* lb    = (const float*)d_in[2];
    const float* ub    = (const float*)d_in[3];
    const float* W1l   = (const float*)d_in[4];
    const float* b1l   = (const float*)d_in[5];
    const float* W1r   = (const float*)d_in[6];
    const float* b1r   = (const float*)d_in[7];
    const float* att1  = (const float*)d_in[8];
    const float* bias1 = (const float*)d_in[9];
    const float* W2l   = (const float*)d_in[10];
    const float* b2l   = (const float*)d_in[11];
    const float* W2r   = (const float*)d_in[12];
    const float* b2r   = (const float*)d_in[13];
    const float* att2  = (const float*)d_in[14];
    const float* bias2 = (const float*)d_in[15];
    const float* W3    = (const float*)d_in[16];
    const float* b3    = (const float*)d_in[17];
    float* out = (float*)d_out;

    int n = in_sizes[0] / 16;
    int E = in_sizes[1] / 2;
    const int* src = ei;
    const int* dst = ei + E;

    int et = E + n;
    int eb256   = (et + 255) / 256;
    int gblocks = (n + 31) / 32;
    int nodeb   = (n + 3) / 4;           // 4 nodes per 256-thread block

    // kernel 0: gemm1 (with fused normalization) + dst histogram
    gemm1_hist<<<gblocks + eb256, 256>>>(x, lb, ub, W1l, b1l, W1r, b1r,
                                         dst, E, n, gblocks);
    // kernels 1-2: scan (self-zeroing) + scatter
    scan_kernel<<<1, 1024>>>(n);
    scatter_kernel<<<eb256, 256>>>(src, dst, E, n);

    // kernel 3 (profiled slot): GAT layer 1
    gat_layer1<<<nodeb, 256>>>(att1, bias1, n);

    // Layer 2
    gemm2_dual<<<(n + 63) / 64, 512>>>(W2l, b2l, W2r, b2r, n);
    gat_layer2<<<nodeb, 256>>>(att2, bias2, W3, b3, out, n);
}